// round 3
// baseline (speedup 1.0000x reference)
#include <cuda_runtime.h>
#include <cstdint>

#define EPSV 1e-6f

// ---------------- scratch (__device__ globals: allocation-free) ----------------
__device__ float g_Q[2][8][64][65536];      // normalized Q per branch   (268 MB)
__device__ float g_cat[8][128][65536];      // concat(a1,a2) NCHW        (268 MB)
__device__ float g_mat[2][8][64][64];       // M[m][c] = sum_n K[m,n]V[c,n]
__device__ float g_ksum[2][8][64];
__device__ float g_vsum[2][8][64];
__device__ float g_P[2][8][64][64];         // P[i][m] = sum_c rw[i][c]*M[m][c]
__device__ float g_u[2][8][64];             // u[i] = rw[i][:]. vsum
__device__ float g_dvec[2][8][64];          // ksum + EPS
__device__ float g_wT[2][3][64][64];        // transposed q/k/v weights [br][p][c][ch]
__device__ float g_wconv[128 * 9 * 64];     // conv weights as [i*9+tap][o]

// ---------------- K0: zero reduction buffers (every replay) ----------------
__global__ __launch_bounds__(256) void k_zero() {
    int tid = blockIdx.x * 256 + threadIdx.x;
    int stride = gridDim.x * 256;
    float* m = &g_mat[0][0][0][0];
    for (int i = tid; i < 2 * 8 * 64 * 64; i += stride) m[i] = 0.f;
    float* ks = &g_ksum[0][0][0];
    float* vs = &g_vsum[0][0][0];
    for (int i = tid; i < 2 * 8 * 64; i += stride) { ks[i] = 0.f; vs[i] = 0.f; }
}

// ---------------- Kpre: transpose weights once per launch ----------------
__global__ __launch_bounds__(256) void k_pre(
    const float* __restrict__ q1w, const float* __restrict__ k1w, const float* __restrict__ v1w,
    const float* __restrict__ q2w, const float* __restrict__ k2w, const float* __restrict__ v2w,
    const float* __restrict__ catw) {
    int tid = blockIdx.x * 256 + threadIdx.x;
    int stride = gridDim.x * 256;
    // q/k/v weights: src [ch][c] 64x64 -> g_wT[br][p][c][ch]
    for (int i = tid; i < 6 * 4096; i += stride) {
        int w = i >> 12, e = i & 4095;
        int ch = e >> 6, c = e & 63;
        const float* src;
        switch (w) {
            case 0: src = q1w; break; case 1: src = k1w; break; case 2: src = v1w; break;
            case 3: src = q2w; break; case 4: src = k2w; break; default: src = v2w; break;
        }
        g_wT[w / 3][w % 3][c][ch] = src[ch * 64 + c];
    }
    // conv weights: src [o][i][ky][kx] -> g_wconv[(i*9+ky*3+kx)*64 + o]
    for (int i = tid; i < 64 * 1152; i += stride) {
        int o = i / 1152, r = i % 1152;
        g_wconv[r * 64 + o] = catw[i];
    }
}

// ---------------- K1: projections + l2norm + stats (tile = 128 px) ----------------
// smem layout (floats): wT[3*4096] | xs[64*128] | qs[64*128] | kst[128*65] | vst[128*65]
//                       | rq[128] | rk[128] | bias[3*64]
#define K1_SMEM_FLOATS (12288 + 8192 + 8192 + 8320 + 8320 + 128 + 128 + 192)
__global__ __launch_bounds__(256) void k1_stats(
    const float* __restrict__ x1, const float* __restrict__ x2,
    const float* __restrict__ q1b, const float* __restrict__ k1b, const float* __restrict__ v1b,
    const float* __restrict__ q2b, const float* __restrict__ k2b, const float* __restrict__ v2b) {
    extern __shared__ float sm[];
    float* wT  = sm;
    float* xs  = sm + 12288;
    float* qs  = sm + 20480;
    float* kst = sm + 28672;
    float* vst = sm + 36992;
    float* rq  = sm + 45312;
    float* rk  = sm + 45440;
    float* bia = sm + 45568;

    const int tile = blockIdx.x, b = blockIdx.y, br = blockIdx.z;
    const int tid = threadIdx.x;
    const int px0 = tile * 128;

    const float* x = (br == 0 ? x1 : x2) + (size_t)b * 64 * 65536 + px0;
    const float* wsrc = &g_wT[br][0][0][0];
    for (int i = tid; i < 12288; i += 256) wT[i] = wsrc[i];
    for (int i = tid; i < 8192; i += 256) {
        int c = i >> 7, p = i & 127;
        xs[i] = x[(size_t)c * 65536 + p];
    }
    if (tid < 192) {
        int p = tid / 64, c = tid % 64;
        const float* bsrc;
        if (br == 0) bsrc = (p == 0 ? q1b : (p == 1 ? k1b : v1b));
        else         bsrc = (p == 0 ? q2b : (p == 1 ? k2b : v2b));
        bia[tid] = bsrc[c];
    }
    __syncthreads();

    // Phase A: 2 channels x 4 px per group.  q -> ch-major, k/v -> px-major (stride 65)
    for (int proj = 0; proj < 3; ++proj) {
        const float* w = wT + proj * 4096;
        const float* bs = bia + proj * 64;
        for (int g = tid; g < 1024; g += 256) {
            int ch0 = (g >> 5) * 2;
            int px  = (g & 31) * 4;
            float b0 = bs[ch0], b1 = bs[ch0 + 1];
            float a[4] = {b0, b0, b0, b0};
            float e[4] = {b1, b1, b1, b1};
            #pragma unroll 8
            for (int c = 0; c < 64; ++c) {
                float w0 = w[c * 64 + ch0];
                float w1 = w[c * 64 + ch0 + 1];
                float4 xv = *(const float4*)&xs[c * 128 + px];
                a[0] += w0 * xv.x; a[1] += w0 * xv.y; a[2] += w0 * xv.z; a[3] += w0 * xv.w;
                e[0] += w1 * xv.x; e[1] += w1 * xv.y; e[2] += w1 * xv.z; e[3] += w1 * xv.w;
            }
            if (proj == 0) {
                *(float4*)&qs[ch0 * 128 + px]       = make_float4(a[0], a[1], a[2], a[3]);
                *(float4*)&qs[(ch0 + 1) * 128 + px] = make_float4(e[0], e[1], e[2], e[3]);
            } else {
                float* d = (proj == 1) ? kst : vst;
                #pragma unroll
                for (int j = 0; j < 4; ++j) {
                    d[(px + j) * 65 + ch0]     = a[j];
                    d[(px + j) * 65 + ch0 + 1] = e[j];
                }
            }
        }
    }
    __syncthreads();

    // l2 norms over channel dim
    if (tid < 128) {
        int px = tid;
        float sq = 0.f, sk = 0.f;
        #pragma unroll 8
        for (int c = 0; c < 64; ++c) {
            float qv = qs[c * 128 + px]; sq += qv * qv;
            float kv = kst[px * 65 + c]; sk += kv * kv;
        }
        rq[px] = rsqrtf(sq);
        rk[px] = rsqrtf(sk);
    }
    __syncthreads();

    // scale q (write to gmem), scale k in place
    float* Qdst = &g_Q[br][b][0][0] + px0;
    for (int i = tid; i < 8192; i += 256) {
        int c = i >> 7, p = i & 127;
        float qn = qs[i] * rq[p];
        Qdst[(size_t)c * 65536 + p] = qn;
        kst[p * 65 + c] *= rk[p];
    }
    __syncthreads();

    // M[m][c] += sum_px k[m,px] * v[c,px]
    // thread owns 2 m's x 8 c's (c interleaved: c = cb + 8*j, cb = tid&7)
    // per px: 2 k-LDS + 8 v-LDS for 16 FFMA; v-loads are 8 consecutive addrs
    // shared by 4 lanes each -> conflict-free broadcast.
    {
        int m0 = (tid >> 3) * 2;
        int cb = tid & 7;
        float acc0[8], acc1[8];
        #pragma unroll
        for (int j = 0; j < 8; ++j) { acc0[j] = 0.f; acc1[j] = 0.f; }
        for (int p = 0; p < 128; ++p) {
            float k0 = kst[p * 65 + m0];
            float k1 = kst[p * 65 + m0 + 1];
            const float* vr = &vst[p * 65 + cb];
            #pragma unroll
            for (int j = 0; j < 8; ++j) {
                float v = vr[j * 8];
                acc0[j] += k0 * v;
                acc1[j] += k1 * v;
            }
        }
        #pragma unroll
        for (int j = 0; j < 8; ++j) {
            atomicAdd(&g_mat[br][b][m0][cb + j * 8], acc0[j]);
            atomicAdd(&g_mat[br][b][m0 + 1][cb + j * 8], acc1[j]);
        }
    }
    // ksum / vsum partials
    for (int i = tid; i < 2048; i += 256) {
        int m = i >> 5, q = i & 31;
        float s = 0.f;
        #pragma unroll
        for (int j = 0; j < 4; ++j) s += kst[(q * 4 + j) * 65 + m];
        atomicAdd(&g_ksum[br][b][m], s);
    }
    for (int i = tid; i < 2048; i += 256) {
        int m = i >> 5, q = i & 31;
        float s = 0.f;
        #pragma unroll
        for (int j = 0; j < 4; ++j) s += vst[(q * 4 + j) * 65 + m];
        atomicAdd(&g_vsum[br][b][m], s);
    }
}

// ---------------- K2: fold r-projection: P = rw * M^T, u = rw * vsum ----------------
__global__ __launch_bounds__(256) void k2_prep(
    const float* __restrict__ r1w, const float* __restrict__ r2w) {
    __shared__ float matS[64][64];
    __shared__ float rwS[64][64];
    __shared__ float vsS[64];
    int id = blockIdx.x;
    int br = id >> 3, b = id & 7;
    int tid = threadIdx.x;
    const float* rw = (br == 0) ? r1w : r2w;
    for (int i = tid; i < 4096; i += 256) {
        (&matS[0][0])[i] = (&g_mat[br][b][0][0])[i];
        (&rwS[0][0])[i]  = rw[i];
    }
    if (tid < 64) vsS[tid] = g_vsum[br][b][tid];
    __syncthreads();
    for (int e = tid; e < 4096; e += 256) {
        int i = e >> 6, m = e & 63;
        float s = 0.f;
        #pragma unroll 8
        for (int c = 0; c < 64; ++c) s += rwS[i][c] * matS[m][c];
        g_P[br][b][i][m] = s;
    }
    if (tid < 64) {
        float s = 0.f;
        #pragma unroll 8
        for (int c = 0; c < 64; ++c) s += rwS[tid][c] * vsS[c];
        g_u[br][b][tid] = s;
        g_dvec[br][b][tid] = g_ksum[br][b][tid] + EPSV;
    }
}

// ---------------- K3: cat channels = denom*(u + P@Q) + rb ----------------
// smem: qs[64*128] | Ps[64*64] | us[64] | dv[64] | rbs[64] | dsm[128]
#define K3_SMEM_FLOATS (8192 + 4096 + 64 + 64 + 64 + 128)
__global__ __launch_bounds__(256) void k3_cat(
    const float* __restrict__ r1b, const float* __restrict__ r2b) {
    extern __shared__ float sm[];
    float* qs  = sm;
    float* Ps  = sm + 8192;
    float* us  = sm + 12288;
    float* dv  = sm + 12352;
    float* rbs = sm + 12416;
    float* dsm = sm + 12480;

    const int tile = blockIdx.x, b = blockIdx.y, br = blockIdx.z;
    const int tid = threadIdx.x;
    const int px0 = tile * 128;

    const float* Qsrc = &g_Q[br][b][0][0] + px0;
    for (int i = tid; i < 8192; i += 256) {
        int c = i >> 7, p = i & 127;
        qs[i] = Qsrc[(size_t)c * 65536 + p];
    }
    const float* Psrc = &g_P[br][b][0][0];
    for (int i = tid; i < 4096; i += 256) Ps[i] = Psrc[i];
    if (tid < 64) {
        us[tid]  = g_u[br][b][tid];
        dv[tid]  = g_dvec[br][b][tid];
        rbs[tid] = (br == 0 ? r1b : r2b)[tid];
    }
    __syncthreads();

    if (tid < 128) {
        int px = tid;
        float s = 65536.0f;
        #pragma unroll 8
        for (int m = 0; m < 64; ++m) s += dv[m] * qs[m * 128 + px];
        dsm[px] = 1.0f / s;
    }
    __syncthreads();

    float* dst = &g_cat[b][br * 64][0] + px0;
    for (int g = tid; g < 1024; g += 256) {
        int i0 = (g >> 5) * 2;
        int px = (g & 31) * 4;
        float u0 = us[i0], u1 = us[i0 + 1];
        float a[4] = {u0, u0, u0, u0};
        float e[4] = {u1, u1, u1, u1};
        #pragma unroll 8
        for (int m = 0; m < 64; ++m) {
            float p0 = Ps[i0 * 64 + m];
            float p1 = Ps[(i0 + 1) * 64 + m];
            float4 qv = *(const float4*)&qs[m * 128 + px];
            a[0] += p0 * qv.x; a[1] += p0 * qv.y; a[2] += p0 * qv.z; a[3] += p0 * qv.w;
            e[0] += p1 * qv.x; e[1] += p1 * qv.y; e[2] += p1 * qv.z; e[3] += p1 * qv.w;
        }
        float4 d4 = *(const float4*)&dsm[px];
        float rb0 = rbs[i0], rb1 = rbs[i0 + 1];
        float4 o0 = make_float4(a[0] * d4.x + rb0, a[1] * d4.y + rb0,
                                a[2] * d4.z + rb0, a[3] * d4.w + rb0);
        float4 o1 = make_float4(e[0] * d4.x + rb1, e[1] * d4.y + rb1,
                                e[2] * d4.z + rb1, e[3] * d4.w + rb1);
        *(float4*)&dst[(size_t)i0 * 65536 + px]       = o0;
        *(float4*)&dst[(size_t)(i0 + 1) * 65536 + px] = o1;
    }
}

// ---------------- K4: 3x3 conv 128->64, SAME, tile 8y x 32x, 4 ci-chunks of 32 ----------------
// smem: in_s[32][10][34] (10880) | w_s[288][64] (18432)
#define K4_SMEM_FLOATS (10880 + 18432)
__global__ __launch_bounds__(256) void k4_conv(
    const float* __restrict__ catb, float* __restrict__ out) {
    extern __shared__ float sm[];
    float* in_s = sm;
    float* w_s  = sm + 10880;

    const int tid = threadIdx.x;
    const int tx = tid & 31, ty = tid >> 5;
    const int x0 = blockIdx.x * 32;
    const int y0 = blockIdx.y * 8;
    const int b  = blockIdx.z;

    float acc[64];
    #pragma unroll
    for (int o = 0; o < 64; ++o) acc[o] = __ldg(&catb[o]);

    for (int ci = 0; ci < 4; ++ci) {
        __syncthreads();
        // stage input tile with halo
        for (int i = tid; i < 10880; i += 256) {
            int ch = i / 340;
            int r  = i % 340;
            int yy = r / 34, xx = r % 34;
            int gy = y0 - 1 + yy;
            int gx = x0 - 1 + xx;
            float v = 0.f;
            if ((unsigned)gy < 256u && (unsigned)gx < 256u)
                v = g_cat[b][ci * 32 + ch][gy * 256 + gx];
            in_s[i] = v;
        }
        // stage weights (already [i*9+t][o] in gmem -> fully coalesced)
        const float* wsrc = g_wconv + (size_t)ci * 32 * 9 * 64;
        for (int i = tid; i < 18432; i += 256) w_s[i] = wsrc[i];
        __syncthreads();

        for (int il = 0; il < 32; ++il) {
            #pragma unroll
            for (int ky = 0; ky < 3; ++ky) {
                const float* irow = &in_s[il * 340 + (ty + ky) * 34 + tx];
                float xv0 = irow[0], xv1 = irow[1], xv2 = irow[2];
                const float* wr = &w_s[(il * 9 + ky * 3) * 64];
                #pragma unroll
                for (int o = 0; o < 64; o += 4) {
                    float4 wa = *(const float4*)&wr[o];
                    float4 wb = *(const float4*)&wr[64 + o];
                    float4 wc = *(const float4*)&wr[128 + o];
                    acc[o + 0] += wa.x * xv0 + wb.x * xv1 + wc.x * xv2;
                    acc[o + 1] += wa.y * xv0 + wb.y * xv1 + wc.y * xv2;
                    acc[o + 2] += wa.z * xv0 + wb.z * xv1 + wc.z * xv2;
                    acc[o + 3] += wa.w * xv0 + wb.w * xv1 + wc.w * xv2;
                }
            }
        }
    }

    float* op = out + (size_t)b * 64 * 65536 + (y0 + ty) * 256 + x0 + tx;
    #pragma unroll
    for (int o = 0; o < 64; ++o) op[(size_t)o * 65536] = acc[o];
}

// ---------------- launch ----------------
extern "C" void kernel_launch(void* const* d_in, const int* in_sizes, int n_in,
                              void* d_out, int out_size) {
    const float* t1   = (const float*)d_in[0];
    const float* t2   = (const float*)d_in[1];
    const float* q1w  = (const float*)d_in[2];
    const float* q1b  = (const float*)d_in[3];
    const float* k1w  = (const float*)d_in[4];
    const float* k1b  = (const float*)d_in[5];
    const float* v1w  = (const float*)d_in[6];
    const float* v1b  = (const float*)d_in[7];
    const float* r1w  = (const float*)d_in[8];
    const float* r1b  = (const float*)d_in[9];
    const float* q2w  = (const float*)d_in[10];
    const float* q2b  = (const float*)d_in[11];
    const float* k2w  = (const float*)d_in[12];
    const float* k2b  = (const float*)d_in[13];
    const float* v2w  = (const float*)d_in[14];
    const float* v2b  = (const float*)d_in[15];
    const float* r2w  = (const float*)d_in[16];
    const float* r2b  = (const float*)d_in[17];
    const float* catw = (const float*)d_in[18];
    const float* catb = (const float*)d_in[19];
    float* out = (float*)d_out;

    cudaFuncSetAttribute(k1_stats, cudaFuncAttributeMaxDynamicSharedMemorySize,
                         K1_SMEM_FLOATS * 4);
    cudaFuncSetAttribute(k3_cat, cudaFuncAttributeMaxDynamicSharedMemorySize,
                         K3_SMEM_FLOATS * 4);
    cudaFuncSetAttribute(k4_conv, cudaFuncAttributeMaxDynamicSharedMemorySize,
                         K4_SMEM_FLOATS * 4);

    k_zero<<<64, 256>>>();
    k_pre<<<128, 256>>>(q1w, k1w, v1w, q2w, k2w, v2w, catw);

    dim3 g1(512, 8, 2);
    k1_stats<<<g1, 256, K1_SMEM_FLOATS * 4>>>(t1, t2, q1b, k1b, v1b, q2b, k2b, v2b);

    k2_prep<<<16, 256>>>(r1w, r2w);

    dim3 g3(512, 8, 2);
    k3_cat<<<g3, 256, K3_SMEM_FLOATS * 4>>>(r1b, r2b);

    dim3 g4(8, 32, 8);
    k4_conv<<<g4, 256, K4_SMEM_FLOATS * 4>>>(catb, out);
}

// round 12
// speedup vs baseline: 1.2234x; 1.2234x over previous
#include <cuda_runtime.h>
#include <cuda_fp16.h>
#include <cstdint>

#define EPSV 1e-6f

// ===== mma.sync helpers (plain PTX, works on sm_103 target) =====
__device__ __forceinline__ void ldsm4(uint32_t& r0, uint32_t& r1, uint32_t& r2, uint32_t& r3, uint32_t a) {
    asm volatile("ldmatrix.sync.aligned.m8n8.x4.shared.b16 {%0,%1,%2,%3}, [%4];"
                 : "=r"(r0), "=r"(r1), "=r"(r2), "=r"(r3) : "r"(a));
}
__device__ __forceinline__ void ldsm2(uint32_t& r0, uint32_t& r1, uint32_t a) {
    asm volatile("ldmatrix.sync.aligned.m8n8.x2.shared.b16 {%0,%1}, [%2];"
                 : "=r"(r0), "=r"(r1) : "r"(a));
}
__device__ __forceinline__ void mma16816(float* c, const uint32_t* a, uint32_t b0, uint32_t b1) {
    asm volatile("mma.sync.aligned.m16n8k16.row.col.f32.f16.f16.f32 "
                 "{%0,%1,%2,%3}, {%4,%5,%6,%7}, {%8,%9}, {%0,%1,%2,%3};"
                 : "+f"(c[0]), "+f"(c[1]), "+f"(c[2]), "+f"(c[3])
                 : "r"(a[0]), "r"(a[1]), "r"(a[2]), "r"(a[3]), "r"(b0), "r"(b1));
}
__device__ __forceinline__ uint32_t smem_u32(const void* p) {
    uint32_t a;
    asm("{ .reg .u64 t; cvta.to.shared.u64 t, %1; cvt.u32.u64 %0, t; }" : "=r"(a) : "l"(p));
    return a;
}
// 32B logical row r, 16B half h -> conflict-free interleaved offset
__device__ __forceinline__ int off_half(int r, int h) {
    return (r * 2 + (h ^ ((r >> 2) & 1))) << 4;
}

// ===== scratch =====
__device__ float  g_Q[2][8][64][65536];
__device__ __half g_cat_h[8][128][258][258];  // fp16 cat, 1px zero border
__device__ float  g_mat[2][8][64][64];
__device__ float  g_ksum[2][8][64];
__device__ float  g_vsum[2][8][64];
__device__ float  g_P[2][8][64][64];
__device__ float  g_u[2][8][64];
__device__ float  g_dvec[2][8][64];
__device__ float  g_wT[2][3][64][64];
__device__ __half g_wconv_h[8 * 9 * 64 * 16];  // [chunk][tap][n64][k16]

__global__ __launch_bounds__(256) void k_zero() {
    int tid = blockIdx.x * 256 + threadIdx.x, stride = gridDim.x * 256;
    float* m = &g_mat[0][0][0][0];
    for (int i = tid; i < 2 * 8 * 64 * 64; i += stride) m[i] = 0.f;
    float* ks = &g_ksum[0][0][0]; float* vs = &g_vsum[0][0][0];
    for (int i = tid; i < 2 * 8 * 64; i += stride) { ks[i] = 0.f; vs[i] = 0.f; }
    const __half hz = __float2half(0.f);
    for (int i = tid; i < 1024 * 1028; i += stride) {
        int plane = i / 1028, e = i % 1028, y, x;
        if (e < 258)      { y = 0;           x = e; }
        else if (e < 516) { y = 257;         x = e - 258; }
        else if (e < 772) { y = e - 516 + 1; x = 0; }
        else              { y = e - 772 + 1; x = 257; }
        (&g_cat_h[0][0][0][0])[((size_t)plane * 258 + y) * 258 + x] = hz;
    }
}

__global__ __launch_bounds__(256) void k_pre(
    const float* __restrict__ q1w, const float* __restrict__ k1w, const float* __restrict__ v1w,
    const float* __restrict__ q2w, const float* __restrict__ k2w, const float* __restrict__ v2w,
    const float* __restrict__ catw) {
    int tid = blockIdx.x * 256 + threadIdx.x, stride = gridDim.x * 256;
    for (int i = tid; i < 6 * 4096; i += stride) {
        int w = i >> 12, e = i & 4095, ch = e >> 6, c = e & 63;
        const float* src;
        switch (w) {
            case 0: src = q1w; break; case 1: src = k1w; break; case 2: src = v1w; break;
            case 3: src = q2w; break; case 4: src = k2w; break; default: src = v2w; break;
        }
        g_wT[w / 3][w % 3][c][ch] = src[ch * 64 + c];
    }
    // conv weights -> [chunk8][tap9][n64][k16] fp16
    for (int i = tid; i < 8 * 9 * 64 * 16; i += stride) {
        int chunk = i / 9216, r1 = i % 9216;
        int tap = r1 / 1024, r2 = r1 % 1024;
        int n = r2 >> 4, k = r2 & 15;
        g_wconv_h[i] = __float2half(catw[(n * 128 + chunk * 16 + k) * 9 + tap]);
    }
}

__global__ void k_dummy() {}

// ===== K1: projections + l2norm + stats (unchanged scalar) =====
#define K1_SMEM_FLOATS (12288 + 8192 + 8192 + 8320 + 8320 + 128 + 128 + 192)
__global__ __launch_bounds__(256) void k1_stats(
    const float* __restrict__ x1, const float* __restrict__ x2,
    const float* __restrict__ q1b, const float* __restrict__ k1b, const float* __restrict__ v1b,
    const float* __restrict__ q2b, const float* __restrict__ k2b, const float* __restrict__ v2b) {
    extern __shared__ float sm[];
    float* wT = sm;            float* xs = sm + 12288;  float* qs = sm + 20480;
    float* kst = sm + 28672;   float* vst = sm + 36992;
    float* rq = sm + 45312;    float* rk = sm + 45440;  float* bia = sm + 45568;
    const int tile = blockIdx.x, b = blockIdx.y, br = blockIdx.z;
    const int tid = threadIdx.x, px0 = tile * 128;

    const float* x = (br == 0 ? x1 : x2) + (size_t)b * 64 * 65536 + px0;
    const float* wsrc = &g_wT[br][0][0][0];
    for (int i = tid; i < 12288; i += 256) wT[i] = wsrc[i];
    for (int i = tid; i < 8192; i += 256) { int c = i >> 7, p = i & 127; xs[i] = x[(size_t)c * 65536 + p]; }
    if (tid < 192) {
        int p = tid / 64, c = tid % 64;
        const float* bsrc;
        if (br == 0) bsrc = (p == 0 ? q1b : (p == 1 ? k1b : v1b));
        else         bsrc = (p == 0 ? q2b : (p == 1 ? k2b : v2b));
        bia[tid] = bsrc[c];
    }
    __syncthreads();

    for (int proj = 0; proj < 3; ++proj) {
        const float* w = wT + proj * 4096;
        const float* bs = bia + proj * 64;
        for (int g = tid; g < 1024; g += 256) {
            int ch0 = (g >> 5) * 2, px = (g & 31) * 4;
            float b0 = bs[ch0], b1 = bs[ch0 + 1];
            float a[4] = {b0, b0, b0, b0}, e[4] = {b1, b1, b1, b1};
            #pragma unroll 8
            for (int c = 0; c < 64; ++c) {
                float w0 = w[c * 64 + ch0], w1 = w[c * 64 + ch0 + 1];
                float4 xv = *(const float4*)&xs[c * 128 + px];
                a[0] += w0 * xv.x; a[1] += w0 * xv.y; a[2] += w0 * xv.z; a[3] += w0 * xv.w;
                e[0] += w1 * xv.x; e[1] += w1 * xv.y; e[2] += w1 * xv.z; e[3] += w1 * xv.w;
            }
            if (proj == 0) {
                *(float4*)&qs[ch0 * 128 + px]       = make_float4(a[0], a[1], a[2], a[3]);
                *(float4*)&qs[(ch0 + 1) * 128 + px] = make_float4(e[0], e[1], e[2], e[3]);
            } else {
                float* d = (proj == 1) ? kst : vst;
                #pragma unroll
                for (int j = 0; j < 4; ++j) { d[(px + j) * 65 + ch0] = a[j]; d[(px + j) * 65 + ch0 + 1] = e[j]; }
            }
        }
    }
    __syncthreads();

    if (tid < 128) {
        int px = tid; float sq = 0.f, sk = 0.f;
        #pragma unroll 8
        for (int c = 0; c < 64; ++c) {
            float qv = qs[c * 128 + px]; sq += qv * qv;
            float kv = kst[px * 65 + c]; sk += kv * kv;
        }
        rq[px] = rsqrtf(sq); rk[px] = rsqrtf(sk);
    }
    __syncthreads();

    float* Qdst = &g_Q[br][b][0][0] + px0;
    for (int i = tid; i < 8192; i += 256) {
        int c = i >> 7, p = i & 127;
        Qdst[(size_t)c * 65536 + p] = qs[i] * rq[p];
        kst[p * 65 + c] *= rk[p];
    }
    __syncthreads();

    {
        int m0 = (tid >> 3) * 2, cb = tid & 7;
        float acc0[8], acc1[8];
        #pragma unroll
        for (int j = 0; j < 8; ++j) { acc0[j] = 0.f; acc1[j] = 0.f; }
        for (int p = 0; p < 128; ++p) {
            float k0 = kst[p * 65 + m0], k1 = kst[p * 65 + m0 + 1];
            const float* vr = &vst[p * 65 + cb];
            #pragma unroll
            for (int j = 0; j < 8; ++j) { float v = vr[j * 8]; acc0[j] += k0 * v; acc1[j] += k1 * v; }
        }
        #pragma unroll
        for (int j = 0; j < 8; ++j) {
            atomicAdd(&g_mat[br][b][m0][cb + j * 8], acc0[j]);
            atomicAdd(&g_mat[br][b][m0 + 1][cb + j * 8], acc1[j]);
        }
    }
    for (int i = tid; i < 2048; i += 256) {
        int m = i >> 5, q = i & 31; float s = 0.f;
        #pragma unroll
        for (int j = 0; j < 4; ++j) s += kst[(q * 4 + j) * 65 + m];
        atomicAdd(&g_ksum[br][b][m], s);
    }
    for (int i = tid; i < 2048; i += 256) {
        int m = i >> 5, q = i & 31; float s = 0.f;
        #pragma unroll
        for (int j = 0; j < 4; ++j) s += vst[(q * 4 + j) * 65 + m];
        atomicAdd(&g_vsum[br][b][m], s);
    }
}

// ===== K2 =====
__global__ __launch_bounds__(256) void k2_prep(const float* __restrict__ r1w, const float* __restrict__ r2w) {
    __shared__ float matS[64][64], rwS[64][64], vsS[64];
    int id = blockIdx.x, br = id >> 3, b = id & 7, tid = threadIdx.x;
    const float* rw = (br == 0) ? r1w : r2w;
    for (int i = tid; i < 4096; i += 256) { (&matS[0][0])[i] = (&g_mat[br][b][0][0])[i]; (&rwS[0][0])[i] = rw[i]; }
    if (tid < 64) vsS[tid] = g_vsum[br][b][tid];
    __syncthreads();
    for (int e = tid; e < 4096; e += 256) {
        int i = e >> 6, m = e & 63; float s = 0.f;
        #pragma unroll 8
        for (int c = 0; c < 64; ++c) s += rwS[i][c] * matS[m][c];
        g_P[br][b][i][m] = s;
    }
    if (tid < 64) {
        float s = 0.f;
        #pragma unroll 8
        for (int c = 0; c < 64; ++c) s += rwS[tid][c] * vsS[c];
        g_u[br][b][tid] = s;
        g_dvec[br][b][tid] = g_ksum[br][b][tid] + EPSV;
    }
}

// ===== K3: cat = denom*(u + P@Q) + rb -> fp16 padded =====
#define K3_SMEM_FLOATS (8192 + 4096 + 64 + 64 + 64 + 128)
__global__ __launch_bounds__(256) void k3_cat(const float* __restrict__ r1b, const float* __restrict__ r2b) {
    extern __shared__ float sm[];
    float* qs = sm;           float* Ps = sm + 8192;   float* us = sm + 12288;
    float* dv = sm + 12352;   float* rbs = sm + 12416; float* dsm = sm + 12480;
    const int tile = blockIdx.x, b = blockIdx.y, br = blockIdx.z;
    const int tid = threadIdx.x, px0 = tile * 128;

    const float* Qsrc = &g_Q[br][b][0][0] + px0;
    for (int i = tid; i < 8192; i += 256) { int c = i >> 7, p = i & 127; qs[i] = Qsrc[(size_t)c * 65536 + p]; }
    const float* Psrc = &g_P[br][b][0][0];
    for (int i = tid; i < 4096; i += 256) Ps[i] = Psrc[i];
    if (tid < 64) { us[tid] = g_u[br][b][tid]; dv[tid] = g_dvec[br][b][tid]; rbs[tid] = (br == 0 ? r1b : r2b)[tid]; }
    __syncthreads();

    if (tid < 128) {
        int px = tid; float s = 65536.0f;
        #pragma unroll 8
        for (int m = 0; m < 64; ++m) s += dv[m] * qs[m * 128 + px];
        dsm[px] = 1.0f / s;
    }
    __syncthreads();

    const int y = px0 >> 8, xb = px0 & 255;
    for (int g = tid; g < 1024; g += 256) {
        int i0 = (g >> 5) * 2, px = (g & 31) * 4;
        float u0 = us[i0], u1 = us[i0 + 1];
        float a[4] = {u0, u0, u0, u0}, e[4] = {u1, u1, u1, u1};
        #pragma unroll 8
        for (int m = 0; m < 64; ++m) {
            float p0 = Ps[i0 * 64 + m], p1 = Ps[(i0 + 1) * 64 + m];
            float4 qv = *(const float4*)&qs[m * 128 + px];
            a[0] += p0 * qv.x; a[1] += p0 * qv.y; a[2] += p0 * qv.z; a[3] += p0 * qv.w;
            e[0] += p1 * qv.x; e[1] += p1 * qv.y; e[2] += p1 * qv.z; e[3] += p1 * qv.w;
        }
        float4 d4 = *(const float4*)&dsm[px];
        float rb0 = rbs[i0], rb1 = rbs[i0 + 1];
        __half* d0 = &g_cat_h[b][br * 64 + i0][y + 1][xb + px + 1];
        __half* d1 = d0 + 258 * 258;
        d0[0] = __float2half(a[0] * d4.x + rb0); d0[1] = __float2half(a[1] * d4.y + rb0);
        d0[2] = __float2half(a[2] * d4.z + rb0); d0[3] = __float2half(a[3] * d4.w + rb0);
        d1[0] = __float2half(e[0] * d4.x + rb1); d1[1] = __float2half(e[1] * d4.y + rb1);
        d1[2] = __float2half(e[2] * d4.z + rb1); d1[3] = __float2half(e[3] * d4.w + rb1);
    }
}

// ===== K4: 3x3 conv 128->64 via mma.sync implicit GEMM =====
// CTA tile 8y x 32x; warp w = row y0+w, M=32 px, N=64.
// smem: in_s 340 rows x 32B (halo tile, per ci-chunk16) | w_s 576 rows x 32B ([tap][n][k16])
#define K4_SMEM_BYTES (10880 + 18432)
__global__ __launch_bounds__(256, 2) void k4_conv_mma(const float* __restrict__ catb, float* __restrict__ out) {
    extern __shared__ char sm4[];
    char* in_p = sm4;
    char* w_p  = sm4 + 10880;
    const uint32_t in_b = smem_u32(in_p);
    const uint32_t w_b  = in_b + 10880;
    const int tid = threadIdx.x, w = tid >> 5, lane = tid & 31;
    const int x0 = blockIdx.x * 32, y0 = blockIdx.y * 8, b = blockIdx.z;

    float acc[2][8][4];
    #pragma unroll
    for (int mi = 0; mi < 2; ++mi)
        #pragma unroll
        for (int nj = 0; nj < 8; ++nj)
            #pragma unroll
            for (int q = 0; q < 4; ++q) acc[mi][nj][q] = 0.f;

    for (int chunk = 0; chunk < 8; ++chunk) {
        __syncthreads();
        // stage weights: [tap][n][k16] rows, interleaved halves
        {
            const uint32_t* wsrc = (const uint32_t*)(g_wconv_h + (size_t)chunk * 9216);
            for (int i = tid; i < 4608; i += 256) {
                int r = i >> 3, j = i & 7;
                *(uint32_t*)(w_p + off_half(r, j >> 2) + (j & 3) * 4) = wsrc[i];
            }
        }
        // stage input halo tile: rows p = ly*34+lx, cols ci16
        for (int i = tid; i < 5440; i += 256) {
            int pr = i / 34, lx = i % 34;
            int c = pr / 10, ly = pr % 10;
            __half v = g_cat_h[b][chunk * 16 + c][y0 + ly][x0 + lx];
            int p = ly * 34 + lx;
            *(__half*)(in_p + off_half(p, c >> 3) + (c & 7) * 2) = v;
        }
        __syncthreads();

        for (int tap = 0; tap < 9; ++tap) {
            const int dy = tap / 3 - 1, dx = tap % 3 - 1;
            uint32_t a[8];
            const int ml = lane & 15, h = lane >> 4;  // tile half along k
            {
                int p0 = (w + dy + 1) * 34 + (ml + dx + 1);
                ldsm4(a[0], a[1], a[2], a[3], in_b + off_half(p0, h));
                int p1 = p0 + 16;
                ldsm4(a[4], a[5], a[6], a[7], in_b + off_half(p1, h));
            }
            const int rb_n = (lane & 7), hb = (lane >> 3) & 1;
            #pragma unroll
            for (int nj = 0; nj < 8; ++nj) {
                uint32_t b0, b1;
                int rw = tap * 64 + nj * 8 + rb_n;
                ldsm2(b0, b1, w_b + off_half(rw, hb));
                mma16816(acc[0][nj], a, b0, b1);
                mma16816(acc[1][nj], a + 4, b0, b1);
            }
        }
    }

    // epilogue: thread holds (m = lane/4 [+8], n = (lane&3)*2 [+1]) per fragment
    const int mrow = lane >> 2, n0 = (lane & 3) * 2;
    float* op = out + (size_t)b * 64 * 65536 + (y0 + w) * 256 + x0;
    #pragma unroll
    for (int mi = 0; mi < 2; ++mi) {
        #pragma unroll
        for (int nj = 0; nj < 8; ++nj) {
            int o0 = nj * 8 + n0, o1 = o0 + 1;
            int px0p = mi * 16 + mrow, px1p = px0p + 8;
            float bo0 = __ldg(&catb[o0]), bo1 = __ldg(&catb[o1]);
            op[(size_t)o0 * 65536 + px0p] = acc[mi][nj][0] + bo0;
            op[(size_t)o1 * 65536 + px0p] = acc[mi][nj][1] + bo1;
            op[(size_t)o0 * 65536 + px1p] = acc[mi][nj][2] + bo0;
            op[(size_t)o1 * 65536 + px1p] = acc[mi][nj][3] + bo1;
        }
    }
}

// ===== launch =====
extern "C" void kernel_launch(void* const* d_in, const int* in_sizes, int n_in,
                              void* d_out, int out_size) {
    const float* t1   = (const float*)d_in[0];
    const float* t2   = (const float*)d_in[1];
    const float* q1w  = (const float*)d_in[2];
    const float* q1b  = (const float*)d_in[3];
    const float* k1w  = (const float*)d_in[4];
    const float* k1b  = (const float*)d_in[5];
    const float* v1w  = (const float*)d_in[6];
    const float* v1b  = (const float*)d_in[7];
    const float* r1w  = (const float*)d_in[8];
    const float* r1b  = (const float*)d_in[9];
    const float* q2w  = (const float*)d_in[10];
    const float* q2b  = (const float*)d_in[11];
    const float* k2w  = (const float*)d_in[12];
    const float* k2b  = (const float*)d_in[13];
    const float* v2w  = (const float*)d_in[14];
    const float* v2b  = (const float*)d_in[15];
    const float* r2w  = (const float*)d_in[16];
    const float* r2b  = (const float*)d_in[17];
    const float* catw = (const float*)d_in[18];
    const float* catb = (const float*)d_in[19];
    float* out = (float*)d_out;

    cudaFuncSetAttribute(k1_stats, cudaFuncAttributeMaxDynamicSharedMemorySize, K1_SMEM_FLOATS * 4);
    cudaFuncSetAttribute(k3_cat,   cudaFuncAttributeMaxDynamicSharedMemorySize, K3_SMEM_FLOATS * 4);
    cudaFuncSetAttribute(k4_conv_mma, cudaFuncAttributeMaxDynamicSharedMemorySize, K4_SMEM_BYTES);

    k_zero<<<64, 256>>>();
    k_pre<<<128, 256>>>(q1w, k1w, v1w, q2w, k2w, v2w, catw);
    k_dummy<<<1, 32>>>();  // shifts ncu -s5 capture onto k1_stats

    dim3 g1(512, 8, 2);
    k1_stats<<<g1, 256, K1_SMEM_FLOATS * 4>>>(t1, t2, q1b, k1b, v1b, q2b, k2b, v2b);

    k2_prep<<<16, 256>>>(r1w, r2w);

    dim3 g3(512, 8, 2);
    k3_cat<<<g3, 256, K3_SMEM_FLOATS * 4>>>(r1b, r2b);

    dim3 g4(8, 32, 8);
    k4_conv_mma<<<g4, 256, K4_SMEM_BYTES>>>(catb, out);
}